// round 16
// baseline (speedup 1.0000x reference)
#include <cuda_runtime.h>
#include <cuda_fp16.h>
#include <math.h>

#define NN   100000
#define EE   1600000
#define ETOT (EE + NN)
#define INC  128
#define HC   128     // HEADS*OUT_C
#define OC   32
#define HEADS 4
#define NEG_SLOPE 0.2f
#define SCAN_BLK 256
#define WS_STRIDE 132
#define GATHER_BLOCKS 304   // 2 per SM on 152 SMs
#define MTILE 32            // gemm rows per block (2 blocks/SM)

typedef unsigned int uint32;

// ---------------- device scratch (static: no allocations allowed) ----------
__device__ int    g_esrc[ETOT];          // CSR: src ids grouped by dst
__device__ int    g_deg[NN];             // in-degree per node
__device__ int    g_tmp[NN];             // block-local exclusive scan
__device__ int    g_part[1024];          // per-block partial sums
__device__ int    g_rowptr[NN];          // CSR row starts
__device__ int    g_cursor[NN];          // scatter cursors
__device__ __half g_h[NN * HC];          // projected features, fp16 [N,128]
__device__ float  g_as[NN * HEADS];      // per-node src logits (fp32)
__device__ float  g_ad[NN * HEADS];      // per-node dst logits (fp32)

// ---------------- helpers ----------------------------------------------------
__device__ __forceinline__ unsigned int f2h2(float a, float b) {
    __half2 h = __floats2half2_rn(a, b);
    return *(unsigned int*)&h;
}
__device__ __forceinline__ uint32 f2tf32(float v) {
    uint32 u; asm("cvt.rna.tf32.f32 %0, %1;" : "=r"(u) : "f"(v)); return u;
}
__device__ __forceinline__ void mma_tf32(float c[4],
                                         uint32 a0, uint32 a1, uint32 a2, uint32 a3,
                                         uint32 b0, uint32 b1) {
    asm volatile(
        "mma.sync.aligned.m16n8k8.row.col.f32.tf32.tf32.f32 "
        "{%0,%1,%2,%3}, {%4,%5,%6,%7}, {%8,%9}, {%0,%1,%2,%3};"
        : "+f"(c[0]), "+f"(c[1]), "+f"(c[2]), "+f"(c[3])
        : "r"(a0), "r"(a1), "r"(a2), "r"(a3), "r"(b0), "r"(b1));
}

// per-call dtype detection: reads first 64 entries as int64; all-valid => i64
__device__ __forceinline__ int detect64(const void* ei) {
    const long long* p = (const long long*)ei;
    int ok = 1;
    #pragma unroll 1
    for (int q = 0; q < 64; ++q) {
        long long v = p[q];
        if (!(v >= 0 && v < (long long)NN)) { ok = 0; break; }
    }
    return ok;
}

// decode edge i: src s, dst d (self loops appended)
__device__ __forceinline__ void edge_at(const void* ei, int is64, int i, int e,
                                        int& s, int& d) {
    if (i < e) {
        if (is64) {
            const long long* p = (const long long*)ei;
            s = (int)p[i];
            d = (int)p[e + i];
        } else {
            const int* p = (const int*)ei;
            s = p[i];
            d = p[e + i];
        }
    } else {
        s = d = i - e;
    }
}

// ---------------- histogram in-degrees --------------------------------------
__global__ void k_prep(const void* ei, int e, int n) {
    int is64 = detect64(ei);
    int i = blockIdx.x * blockDim.x + threadIdx.x;
    int tot = e + n;
    if (i >= tot) return;
    int s, d;
    edge_at(ei, is64, i, e, s, d);
    atomicAdd(&g_deg[d], 1);
}

// ---------------- scan stage 1 ----------------------------------------------
__global__ void k_scan1(int n) {
    __shared__ int sm[SCAN_BLK];
    int t = threadIdx.x;
    int i = blockIdx.x * SCAN_BLK + t;
    int v = (i < n) ? g_deg[i] : 0;
    sm[t] = v;
    __syncthreads();
    #pragma unroll
    for (int off = 1; off < SCAN_BLK; off <<= 1) {
        int u = (t >= off) ? sm[t - off] : 0;
        __syncthreads();
        sm[t] += u;
        __syncthreads();
    }
    if (i < n) g_tmp[i] = sm[t] - v;
    if (t == SCAN_BLK - 1) g_part[blockIdx.x] = sm[t];
}

// ---------------- scan stage 2+3 --------------------------------------------
__global__ void k_scan23(int n) {
    __shared__ int sm[SCAN_BLK];
    int b = blockIdx.x, t = threadIdx.x;
    int acc = 0;
    for (int j = t; j < b; j += SCAN_BLK) acc += g_part[j];
    sm[t] = acc;
    __syncthreads();
    #pragma unroll
    for (int off = SCAN_BLK / 2; off > 0; off >>= 1) {
        if (t < off) sm[t] += sm[t + off];
        __syncthreads();
    }
    int base = sm[0];
    int i = b * SCAN_BLK + t;
    if (i < n) {
        int r = g_tmp[i] + base;
        g_rowptr[i] = r;
        g_cursor[i] = r;
    }
}

// ---------------- fused tf32-MMA GEMM (+logits) || CSR scatter ---------------
// gemm role: 256 thr = 8 warps = 2 m-tiles(16) x 4 n-quarters(32), MTILE=32
// rows/block => 82.5KB smem => 2 blocks/SM for staging/MMA overlap.
// scatter role (bid%4==3): grid-stride atomic-cursor CSR build.
__global__ void __launch_bounds__(256)
k_gemm_scatter(const float* __restrict__ x, const float* __restrict__ W,
               const float* __restrict__ att_s, const float* __restrict__ att_d,
               const void* ei, int n, int e,
               int nb_gemm, int nb_scat) {
    int bid = blockIdx.x;
    int tid = threadIdx.x;

    if ((bid & 3) == 3) {
        int sid = bid >> 2;
        if (sid >= nb_scat) return;
        int is64 = detect64(ei);
        int etot = e + n;
        int stride = nb_scat * 256;
        for (int i = sid * 256 + tid; i < etot; i += stride) {
            int s, d;
            edge_at(ei, is64, i, e, s, d);
            int pos = atomicAdd(&g_cursor[d], 1);
            g_esrc[pos] = s;
        }
        return;
    }

    int gid = (bid >> 2) * 3 + (bid & 3);
    if (gid >= nb_gemm) return;

    extern __shared__ uint32 smu[];
    uint32* Ws = smu;                      // [128][132] tf32
    uint32* xs = smu + 128 * WS_STRIDE;    // [MTILE][132] tf32

    for (int idx = tid; idx < HC * INC; idx += 256) {
        int nr = idx >> 7, k = idx & 127;
        Ws[nr * WS_STRIDE + k] = f2tf32(W[idx]);
    }
    int row0 = gid * MTILE;
    for (int idx = tid; idx < MTILE * INC; idx += 256) {
        int r = idx >> 7, k = idx & 127;
        float v = (row0 + r < n) ? x[(size_t)row0 * INC + idx] : 0.0f;
        xs[r * WS_STRIDE + k] = f2tf32(v);
    }
    __syncthreads();

    int w    = tid >> 5;
    int lane = tid & 31;
    int qr   = lane >> 2;      // quad row (0..7)
    int qc   = lane & 3;       // quad col (0..3)
    int m0   = (w & 1) * 16;   // 2 m-tiles
    int n0   = (w >> 1) * 32;  // 4 n-quarters (one head each)
    int head = n0 >> 5;

    float acc[4][4];
    #pragma unroll
    for (int nt = 0; nt < 4; ++nt)
        #pragma unroll
        for (int c = 0; c < 4; ++c) acc[nt][c] = 0.0f;

    const uint32* xbase = &xs[(m0 + qr) * WS_STRIDE + qc];
    const uint32* wbase = &Ws[(n0 + qr) * WS_STRIDE + qc];

    #pragma unroll 4
    for (int ks = 0; ks < 16; ++ks) {
        int k0 = ks * 8;
        uint32 a0 = xbase[k0];
        uint32 a2 = xbase[k0 + 4];
        uint32 a1 = xbase[k0 + 8 * WS_STRIDE];
        uint32 a3 = xbase[k0 + 8 * WS_STRIDE + 4];
        #pragma unroll
        for (int nt = 0; nt < 4; ++nt) {
            uint32 b0 = wbase[nt * 8 * WS_STRIDE + k0];
            uint32 b1 = wbase[nt * 8 * WS_STRIDE + k0 + 4];
            mma_tf32(acc[nt], a0, a1, a2, a3, b0, b1);
        }
    }

    // epilogue: fp16 h store + per-head logits (this warp owns exactly 1 head)
    int r0 = row0 + m0 + qr;
    int r1 = r0 + 8;
    float ps0 = 0.f, ps1 = 0.f, pd0 = 0.f, pd1 = 0.f;

    #pragma unroll
    for (int nt = 0; nt < 4; ++nt) {
        int cb = n0 + nt * 8 + 2 * qc;
        if (r0 < n) *(unsigned int*)&g_h[(size_t)r0 * HC + cb] = f2h2(acc[nt][0], acc[nt][1]);
        if (r1 < n) *(unsigned int*)&g_h[(size_t)r1 * HC + cb] = f2h2(acc[nt][2], acc[nt][3]);
        float as0 = __ldg(&att_s[cb]),  as1 = __ldg(&att_s[cb + 1]);
        float ad0 = __ldg(&att_d[cb]),  ad1 = __ldg(&att_d[cb + 1]);
        ps0 += acc[nt][0] * as0 + acc[nt][1] * as1;
        ps1 += acc[nt][2] * as0 + acc[nt][3] * as1;
        pd0 += acc[nt][0] * ad0 + acc[nt][1] * ad1;
        pd1 += acc[nt][2] * ad0 + acc[nt][3] * ad1;
    }
    #pragma unroll
    for (int o = 1; o <= 2; o <<= 1) {
        ps0 += __shfl_xor_sync(0xffffffffu, ps0, o);
        ps1 += __shfl_xor_sync(0xffffffffu, ps1, o);
        pd0 += __shfl_xor_sync(0xffffffffu, pd0, o);
        pd1 += __shfl_xor_sync(0xffffffffu, pd1, o);
    }
    if (qc == 0) {
        if (r0 < n) { g_as[r0 * HEADS + head] = ps0; g_ad[r0 * HEADS + head] = pd0; }
        if (r1 < n) { g_as[r1 * HEADS + head] = ps1; g_ad[r1 * HEADS + head] = pd1; }
    }
}

// ---------------- persistent fused gather + final linear ---------------------
__global__ void __launch_bounds__(512, 2)
k_gather_final(const float* __restrict__ bias,
               const float* __restrict__ Wl,
               const float* __restrict__ bl,
               float* __restrict__ out, int n, int nwarps) {
    __shared__ __half2 Wt2[64 * 32];  // Wt2[kp*32+oc]
    __shared__ float xr[16][128];
    int tid  = threadIdx.x;
    int warp = tid >> 5;
    int lane = tid & 31;
    int gw   = blockIdx.x * 16 + warp;

    for (int idx = tid; idx < OC * HC / 2; idx += 512) {
        int oc = idx >> 6;
        int kp = idx & 63;
        Wt2[kp * 32 + oc] = __floats2half2_rn(Wl[oc * HC + 2 * kp],
                                              Wl[oc * HC + 2 * kp + 1]);
    }
    __syncthreads();

    int hh = lane >> 3;
    const __half* hbase = g_h;

    for (int node = gw; node < n; node += nwarps) {
        int start = g_rowptr[node];
        int deg   = g_deg[node];
        float adv = g_ad[node * HEADS + hh];
        const int* es = &g_esrc[start];

        float sum = 0.0f;
        float ax = 0.f, ay = 0.f, az = 0.f, aw = 0.f;
        int j = 0;
        for (; j + 4 <= deg; j += 4) {
            int s0 = __ldg(es + j), s1 = __ldg(es + j + 1);
            int s2 = __ldg(es + j + 2), s3 = __ldg(es + j + 3);
            float a0 = g_as[s0 * HEADS + hh];
            float a1 = g_as[s1 * HEADS + hh];
            float a2 = g_as[s2 * HEADS + hh];
            float a3 = g_as[s3 * HEADS + hh];
            uint2 v0 = *(const uint2*)&hbase[(size_t)s0 * HC + lane * 4];
            uint2 v1 = *(const uint2*)&hbase[(size_t)s1 * HC + lane * 4];
            uint2 v2 = *(const uint2*)&hbase[(size_t)s2 * HC + lane * 4];
            uint2 v3 = *(const uint2*)&hbase[(size_t)s3 * HC + lane * 4];
            float e0 = a0 + adv; e0 = e0 > 0.f ? e0 : NEG_SLOPE * e0;
            float e1 = a1 + adv; e1 = e1 > 0.f ? e1 : NEG_SLOPE * e1;
            float e2 = a2 + adv; e2 = e2 > 0.f ? e2 : NEG_SLOPE * e2;
            float e3 = a3 + adv; e3 = e3 > 0.f ? e3 : NEG_SLOPE * e3;
            float w0 = __expf(e0), w1 = __expf(e1), w2 = __expf(e2), w3 = __expf(e3);
            sum += (w0 + w1) + (w2 + w3);
            float2 l0 = __half22float2(*(const __half2*)&v0.x);
            float2 u0 = __half22float2(*(const __half2*)&v0.y);
            float2 l1 = __half22float2(*(const __half2*)&v1.x);
            float2 u1 = __half22float2(*(const __half2*)&v1.y);
            float2 l2 = __half22float2(*(const __half2*)&v2.x);
            float2 u2 = __half22float2(*(const __half2*)&v2.y);
            float2 l3 = __half22float2(*(const __half2*)&v3.x);
            float2 u3 = __half22float2(*(const __half2*)&v3.y);
            ax = fmaf(w0, l0.x, fmaf(w1, l1.x, fmaf(w2, l2.x, fmaf(w3, l3.x, ax))));
            ay = fmaf(w0, l0.y, fmaf(w1, l1.y, fmaf(w2, l2.y, fmaf(w3, l3.y, ay))));
            az = fmaf(w0, u0.x, fmaf(w1, u1.x, fmaf(w2, u2.x, fmaf(w3, u3.x, az))));
            aw = fmaf(w0, u0.y, fmaf(w1, u1.y, fmaf(w2, u2.y, fmaf(w3, u3.y, aw))));
        }
        for (; j < deg; ++j) {
            int s0 = __ldg(es + j);
            float a0 = g_as[s0 * HEADS + hh];
            uint2 v0 = *(const uint2*)&hbase[(size_t)s0 * HC + lane * 4];
            float e0 = a0 + adv; e0 = e0 > 0.f ? e0 : NEG_SLOPE * e0;
            float w0 = __expf(e0);
            sum += w0;
            float2 l0 = __half22float2(*(const __half2*)&v0.x);
            float2 u0 = __half22float2(*(const __half2*)&v0.y);
            ax = fmaf(w0, l0.x, ax);
            ay = fmaf(w0, l0.y, ay);
            az = fmaf(w0, u0.x, az);
            aw = fmaf(w0, u0.y, aw);
        }
        float inv = 1.0f / sum;
        float4 bv = *(const float4*)&bias[lane * 4];
        xr[warp][lane * 4 + 0] = fmaf(ax, inv, bv.x);
        xr[warp][lane * 4 + 1] = fmaf(ay, inv, bv.y);
        xr[warp][lane * 4 + 2] = fmaf(az, inv, bv.z);
        xr[warp][lane * 4 + 3] = fmaf(aw, inv, bv.w);
        __syncwarp();

        int oc = lane;
        float accv = 0.0f;
        const float* row = xr[warp];
        #pragma unroll 8
        for (int kp = 0; kp < 64; ++kp) {
            float2 wv = __half22float2(Wt2[kp * 32 + oc]);
            accv = fmaf(row[2 * kp], wv.x, accv);
            accv = fmaf(row[2 * kp + 1], wv.y, accv);
        }
        accv += __ldg(&bl[oc]);
        out[(size_t)node * OC + oc] = accv > 0.0f ? accv : (__expf(accv) - 1.0f);
        __syncwarp();   // xr reuse guard before next node
    }
}

// ---------------- launch -----------------------------------------------------
extern "C" void kernel_launch(void* const* d_in, const int* in_sizes, int n_in,
                              void* d_out, int out_size) {
    const float* x     = (const float*)d_in[0];
    const void*  ei    = d_in[1];
    const float* W     = (const float*)d_in[2];
    const float* att_s = (const float*)d_in[3];
    const float* att_d = (const float*)d_in[4];
    const float* bias  = (const float*)d_in[5];
    const float* Wl    = (const float*)d_in[6];
    const float* bl    = (const float*)d_in[7];
    float* out = (float*)d_out;

    int n = in_sizes[0] / INC;
    int e = in_sizes[1] / 2;
    int etot = e + n;
    int nscan = (n + SCAN_BLK - 1) / SCAN_BLK;

    int nb_gemm = (n + MTILE - 1) / MTILE;
    int nb_scat = (nb_gemm + 2) / 3;
    int nb_fused = 4 * nb_scat;

    static void* deg_ptr = nullptr;
    static int smem_set = 0;
    if (!smem_set) {
        cudaFuncSetAttribute(k_gemm_scatter, cudaFuncAttributeMaxDynamicSharedMemorySize, 100 * 1024);
        cudaGetSymbolAddress(&deg_ptr, g_deg);
        smem_set = 1;
    }
    size_t gemm_smem = (size_t)(128 * WS_STRIDE + MTILE * WS_STRIDE) * sizeof(uint32);

    cudaMemsetAsync(deg_ptr, 0, (size_t)n * sizeof(int));
    k_prep<<<(etot + 255) / 256, 256>>>(ei, e, n);
    k_scan1<<<nscan, SCAN_BLK>>>(n);
    k_scan23<<<nscan, SCAN_BLK>>>(n);
    k_gemm_scatter<<<nb_fused, 256, gemm_smem>>>(x, W, att_s, att_d, ei, n, e, nb_gemm, nb_scat);
    k_gather_final<<<GATHER_BLOCKS, 512>>>(bias, Wl, bl, out, n, GATHER_BLOCKS * 16);
}

// round 17
// speedup vs baseline: 1.3206x; 1.3206x over previous
#include <cuda_runtime.h>
#include <cuda_fp16.h>
#include <math.h>

#define NN   100000
#define EE   1600000
#define ETOT (EE + NN)
#define INC  128
#define HC   128     // HEADS*OUT_C
#define OC   32
#define HEADS 4
#define NEG_SLOPE 0.2f
#define SCAN_BLK 256
#define WS_STRIDE 132
#define GATHER_BLOCKS 304   // 2 per SM on 152 SMs

typedef unsigned int uint32;

// ---------------- device scratch (static: no allocations allowed) ----------
__device__ int    g_esrc[ETOT];          // CSR: src ids grouped by dst
__device__ int    g_deg[NN];             // in-degree per node
__device__ int    g_tmp[NN];             // block-local exclusive scan
__device__ int    g_part[1024];          // per-block partial sums
__device__ int    g_rowptr[NN];          // CSR row starts
__device__ int    g_cursor[NN];          // scatter cursors
__device__ __half g_h[NN * HC];          // projected features, fp16 [N,128]
__device__ float  g_as[NN * HEADS];      // per-node src logits (fp32)
__device__ float  g_ad[NN * HEADS];      // per-node dst logits (fp32)

// ---------------- helpers ----------------------------------------------------
__device__ __forceinline__ unsigned int f2h2(float a, float b) {
    __half2 h = __floats2half2_rn(a, b);
    return *(unsigned int*)&h;
}
__device__ __forceinline__ uint32 f2tf32(float v) {
    uint32 u; asm("cvt.rna.tf32.f32 %0, %1;" : "=r"(u) : "f"(v)); return u;
}
__device__ __forceinline__ void mma_tf32(float c[4],
                                         uint32 a0, uint32 a1, uint32 a2, uint32 a3,
                                         uint32 b0, uint32 b1) {
    asm volatile(
        "mma.sync.aligned.m16n8k8.row.col.f32.tf32.tf32.f32 "
        "{%0,%1,%2,%3}, {%4,%5,%6,%7}, {%8,%9}, {%0,%1,%2,%3};"
        : "+f"(c[0]), "+f"(c[1]), "+f"(c[2]), "+f"(c[3])
        : "r"(a0), "r"(a1), "r"(a2), "r"(a3), "r"(b0), "r"(b1));
}

// per-call dtype detection: reads first 64 entries as int64; all-valid => i64
__device__ __forceinline__ int detect64(const void* ei) {
    const long long* p = (const long long*)ei;
    int ok = 1;
    #pragma unroll 1
    for (int q = 0; q < 64; ++q) {
        long long v = p[q];
        if (!(v >= 0 && v < (long long)NN)) { ok = 0; break; }
    }
    return ok;
}

// decode edge i: src s, dst d (self loops appended)
__device__ __forceinline__ void edge_at(const void* ei, int is64, int i, int e,
                                        int& s, int& d) {
    if (i < e) {
        if (is64) {
            const long long* p = (const long long*)ei;
            s = (int)p[i];
            d = (int)p[e + i];
        } else {
            const int* p = (const int*)ei;
            s = p[i];
            d = p[e + i];
        }
    } else {
        s = d = i - e;
    }
}

// ---------------- histogram in-degrees --------------------------------------
__global__ void k_prep(const void* ei, int e, int n) {
    int is64 = detect64(ei);
    int i = blockIdx.x * blockDim.x + threadIdx.x;
    int tot = e + n;
    if (i >= tot) return;
    int s, d;
    edge_at(ei, is64, i, e, s, d);
    atomicAdd(&g_deg[d], 1);
}

// ---------------- scan stage 1 ----------------------------------------------
__global__ void k_scan1(int n) {
    __shared__ int sm[SCAN_BLK];
    int t = threadIdx.x;
    int i = blockIdx.x * SCAN_BLK + t;
    int v = (i < n) ? g_deg[i] : 0;
    sm[t] = v;
    __syncthreads();
    #pragma unroll
    for (int off = 1; off < SCAN_BLK; off <<= 1) {
        int u = (t >= off) ? sm[t - off] : 0;
        __syncthreads();
        sm[t] += u;
        __syncthreads();
    }
    if (i < n) g_tmp[i] = sm[t] - v;
    if (t == SCAN_BLK - 1) g_part[blockIdx.x] = sm[t];
}

// ---------------- scan stage 2+3 --------------------------------------------
__global__ void k_scan23(int n) {
    __shared__ int sm[SCAN_BLK];
    int b = blockIdx.x, t = threadIdx.x;
    int acc = 0;
    for (int j = t; j < b; j += SCAN_BLK) acc += g_part[j];
    sm[t] = acc;
    __syncthreads();
    #pragma unroll
    for (int off = SCAN_BLK / 2; off > 0; off >>= 1) {
        if (t < off) sm[t] += sm[t + off];
        __syncthreads();
    }
    int base = sm[0];
    int i = b * SCAN_BLK + t;
    if (i < n) {
        int r = g_tmp[i] + base;
        g_rowptr[i] = r;
        g_cursor[i] = r;
    }
}

// ---------------- fused tf32-MMA GEMM (+logits) || CSR scatter ---------------
// R13 structure (MTILE=64, 8 warps = 4 m-tiles x 2 n-halves) with vectorized
// float4/uint4 staging (4x fewer LDG/STS in the staging phase).
__global__ void __launch_bounds__(256)
k_gemm_scatter(const float* __restrict__ x, const float* __restrict__ W,
               const float* __restrict__ att_s, const float* __restrict__ att_d,
               const void* ei, int n, int e,
               int nb_gemm, int nb_scat) {
    int bid = blockIdx.x;
    int tid = threadIdx.x;

    if ((bid & 3) == 3) {
        int sid = bid >> 2;
        if (sid >= nb_scat) return;
        int is64 = detect64(ei);
        int etot = e + n;
        int stride = nb_scat * 256;
        for (int i = sid * 256 + tid; i < etot; i += stride) {
            int s, d;
            edge_at(ei, is64, i, e, s, d);
            int pos = atomicAdd(&g_cursor[d], 1);
            g_esrc[pos] = s;
        }
        return;
    }

    int gid = (bid >> 2) * 3 + (bid & 3);
    if (gid >= nb_gemm) return;

    extern __shared__ uint32 smu[];
    uint32* Ws = smu;                      // [128][132] tf32
    uint32* xs = smu + 128 * WS_STRIDE;    // [64][132]  tf32

    // vectorized W staging: float4 loads, uint4 stores (rows 16B-aligned)
    for (int idx = tid; idx < HC * INC / 4; idx += 256) {
        int p = idx * 4;
        int nr = p >> 7, k = p & 127;
        float4 wv = *(const float4*)&W[p];
        uint4 u = make_uint4(f2tf32(wv.x), f2tf32(wv.y), f2tf32(wv.z), f2tf32(wv.w));
        *(uint4*)&Ws[nr * WS_STRIDE + k] = u;
    }
    int row0 = gid * 64;
    for (int idx = tid; idx < 64 * INC / 4; idx += 256) {
        int p = idx * 4;
        int r = p >> 7, k = p & 127;
        uint4 u;
        if (row0 + r < n) {
            float4 xv = *(const float4*)&x[(size_t)row0 * INC + p];
            u = make_uint4(f2tf32(xv.x), f2tf32(xv.y), f2tf32(xv.z), f2tf32(xv.w));
        } else {
            u = make_uint4(0u, 0u, 0u, 0u);
        }
        *(uint4*)&xs[r * WS_STRIDE + k] = u;
    }
    __syncthreads();

    int w    = tid >> 5;
    int lane = tid & 31;
    int qr   = lane >> 2;
    int qc   = lane & 3;
    int m0   = (w & 3) * 16;
    int n0   = (w >> 2) * 64;

    float acc[8][4];
    #pragma unroll
    for (int nt = 0; nt < 8; ++nt)
        #pragma unroll
        for (int c = 0; c < 4; ++c) acc[nt][c] = 0.0f;

    const uint32* xbase = &xs[(m0 + qr) * WS_STRIDE + qc];
    const uint32* wbase = &Ws[(n0 + qr) * WS_STRIDE + qc];

    #pragma unroll 4
    for (int ks = 0; ks < 16; ++ks) {
        int k0 = ks * 8;
        uint32 a0 = xbase[k0];
        uint32 a2 = xbase[k0 + 4];
        uint32 a1 = xbase[k0 + 8 * WS_STRIDE];
        uint32 a3 = xbase[k0 + 8 * WS_STRIDE + 4];
        #pragma unroll
        for (int nt = 0; nt < 8; ++nt) {
            uint32 b0 = wbase[nt * 8 * WS_STRIDE + k0];
            uint32 b1 = wbase[nt * 8 * WS_STRIDE + k0 + 4];
            mma_tf32(acc[nt], a0, a1, a2, a3, b0, b1);
        }
    }

    int r0 = row0 + m0 + qr;
    int r1 = r0 + 8;
    int h0 = n0 >> 5;
    float ps[2][2] = {{0, 0}, {0, 0}};
    float pd[2][2] = {{0, 0}, {0, 0}};

    #pragma unroll
    for (int nt = 0; nt < 8; ++nt) {
        int cb = n0 + nt * 8 + 2 * qc;
        if (r0 < n) *(unsigned int*)&g_h[(size_t)r0 * HC + cb] = f2h2(acc[nt][0], acc[nt][1]);
        if (r1 < n) *(unsigned int*)&g_h[(size_t)r1 * HC + cb] = f2h2(acc[nt][2], acc[nt][3]);
        float as0 = __ldg(&att_s[cb]),  as1 = __ldg(&att_s[cb + 1]);
        float ad0 = __ldg(&att_d[cb]),  ad1 = __ldg(&att_d[cb + 1]);
        int hi = nt >> 2;
        ps[hi][0] += acc[nt][0] * as0 + acc[nt][1] * as1;
        ps[hi][1] += acc[nt][2] * as0 + acc[nt][3] * as1;
        pd[hi][0] += acc[nt][0] * ad0 + acc[nt][1] * ad1;
        pd[hi][1] += acc[nt][2] * ad0 + acc[nt][3] * ad1;
    }
    #pragma unroll
    for (int hi = 0; hi < 2; ++hi)
        #pragma unroll
        for (int gp = 0; gp < 2; ++gp) {
            #pragma unroll
            for (int o = 1; o <= 2; o <<= 1) {
                ps[hi][gp] += __shfl_xor_sync(0xffffffffu, ps[hi][gp], o);
                pd[hi][gp] += __shfl_xor_sync(0xffffffffu, pd[hi][gp], o);
            }
        }
    if (qc == 0) {
        #pragma unroll
        for (int hi = 0; hi < 2; ++hi) {
            if (r0 < n) { g_as[r0 * HEADS + h0 + hi] = ps[hi][0]; g_ad[r0 * HEADS + h0 + hi] = pd[hi][0]; }
            if (r1 < n) { g_as[r1 * HEADS + h0 + hi] = ps[hi][1]; g_ad[r1 * HEADS + h0 + hi] = pd[hi][1]; }
        }
    }
}

// ---------------- persistent fused gather + final linear ---------------------
__global__ void __launch_bounds__(512, 2)
k_gather_final(const float* __restrict__ bias,
               const float* __restrict__ Wl,
               const float* __restrict__ bl,
               float* __restrict__ out, int n, int nwarps) {
    __shared__ __half2 Wt2[64 * 32];  // Wt2[kp*32+oc]
    __shared__ float xr[16][128];
    int tid  = threadIdx.x;
    int warp = tid >> 5;
    int lane = tid & 31;
    int gw   = blockIdx.x * 16 + warp;

    for (int idx = tid; idx < OC * HC / 2; idx += 512) {
        int oc = idx >> 6;
        int kp = idx & 63;
        Wt2[kp * 32 + oc] = __floats2half2_rn(Wl[oc * HC + 2 * kp],
                                              Wl[oc * HC + 2 * kp + 1]);
    }
    __syncthreads();

    int hh = lane >> 3;
    const __half* hbase = g_h;

    for (int node = gw; node < n; node += nwarps) {
        int start = g_rowptr[node];
        int deg   = g_deg[node];
        float adv = g_ad[node * HEADS + hh];
        const int* es = &g_esrc[start];

        float sum = 0.0f;
        float ax = 0.f, ay = 0.f, az = 0.f, aw = 0.f;
        int j = 0;
        for (; j + 4 <= deg; j += 4) {
            int s0 = __ldg(es + j), s1 = __ldg(es + j + 1);
            int s2 = __ldg(es + j + 2), s3 = __ldg(es + j + 3);
            float a0 = g_as[s0 * HEADS + hh];
            float a1 = g_as[s1 * HEADS + hh];
            float a2 = g_as[s2 * HEADS + hh];
            float a3 = g_as[s3 * HEADS + hh];
            uint2 v0 = *(const uint2*)&hbase[(size_t)s0 * HC + lane * 4];
            uint2 v1 = *(const uint2*)&hbase[(size_t)s1 * HC + lane * 4];
            uint2 v2 = *(const uint2*)&hbase[(size_t)s2 * HC + lane * 4];
            uint2 v3 = *(const uint2*)&hbase[(size_t)s3 * HC + lane * 4];
            float e0 = a0 + adv; e0 = e0 > 0.f ? e0 : NEG_SLOPE * e0;
            float e1 = a1 + adv; e1 = e1 > 0.f ? e1 : NEG_SLOPE * e1;
            float e2 = a2 + adv; e2 = e2 > 0.f ? e2 : NEG_SLOPE * e2;
            float e3 = a3 + adv; e3 = e3 > 0.f ? e3 : NEG_SLOPE * e3;
            float w0 = __expf(e0), w1 = __expf(e1), w2 = __expf(e2), w3 = __expf(e3);
            sum += (w0 + w1) + (w2 + w3);
            float2 l0 = __half22float2(*(const __half2*)&v0.x);
            float2 u0 = __half22float2(*(const __half2*)&v0.y);
            float2 l1 = __half22float2(*(const __half2*)&v1.x);
            float2 u1 = __half22float2(*(const __half2*)&v1.y);
            float2 l2 = __half22float2(*(const __half2*)&v2.x);
            float2 u2 = __half22float2(*(const __half2*)&v2.y);
            float2 l3 = __half22float2(*(const __half2*)&v3.x);
            float2 u3 = __half22float2(*(const __half2*)&v3.y);
            ax = fmaf(w0, l0.x, fmaf(w1, l1.x, fmaf(w2, l2.x, fmaf(w3, l3.x, ax))));
            ay = fmaf(w0, l0.y, fmaf(w1, l1.y, fmaf(w2, l2.y, fmaf(w3, l3.y, ay))));
            az = fmaf(w0, u0.x, fmaf(w1, u1.x, fmaf(w2, u2.x, fmaf(w3, u3.x, az))));
            aw = fmaf(w0, u0.y, fmaf(w1, u1.y, fmaf(w2, u2.y, fmaf(w3, u3.y, aw))));
        }
        for (; j < deg; ++j) {
            int s0 = __ldg(es + j);
            float a0 = g_as[s0 * HEADS + hh];
            uint2 v0 = *(const uint2*)&hbase[(size_t)s0 * HC + lane * 4];
            float e0 = a0 + adv; e0 = e0 > 0.f ? e0 : NEG_SLOPE * e0;
            float w0 = __expf(e0);
            sum += w0;
            float2 l0 = __half22float2(*(const __half2*)&v0.x);
            float2 u0 = __half22float2(*(const __half2*)&v0.y);
            ax = fmaf(w0, l0.x, ax);
            ay = fmaf(w0, l0.y, ay);
            az = fmaf(w0, u0.x, az);
            aw = fmaf(w0, u0.y, aw);
        }
        float inv = 1.0f / sum;
        float4 bv = *(const float4*)&bias[lane * 4];
        xr[warp][lane * 4 + 0] = fmaf(ax, inv, bv.x);
        xr[warp][lane * 4 + 1] = fmaf(ay, inv, bv.y);
        xr[warp][lane * 4 + 2] = fmaf(az, inv, bv.z);
        xr[warp][lane * 4 + 3] = fmaf(aw, inv, bv.w);
        __syncwarp();

        int oc = lane;
        float accv = 0.0f;
        const float* row = xr[warp];
        #pragma unroll 8
        for (int kp = 0; kp < 64; ++kp) {
            float2 wv = __half22float2(Wt2[kp * 32 + oc]);
            accv = fmaf(row[2 * kp], wv.x, accv);
            accv = fmaf(row[2 * kp + 1], wv.y, accv);
        }
        accv += __ldg(&bl[oc]);
        out[(size_t)node * OC + oc] = accv > 0.0f ? accv : (__expf(accv) - 1.0f);
        __syncwarp();   // xr reuse guard before next node
    }
}

// ---------------- launch -----------------------------------------------------
extern "C" void kernel_launch(void* const* d_in, const int* in_sizes, int n_in,
                              void* d_out, int out_size) {
    const float* x     = (const float*)d_in[0];
    const void*  ei    = d_in[1];
    const float* W     = (const float*)d_in[2];
    const float* att_s = (const float*)d_in[3];
    const float* att_d = (const float*)d_in[4];
    const float* bias  = (const float*)d_in[5];
    const float* Wl    = (const float*)d_in[6];
    const float* bl    = (const float*)d_in[7];
    float* out = (float*)d_out;

    int n = in_sizes[0] / INC;
    int e = in_sizes[1] / 2;
    int etot = e + n;
    int nscan = (n + SCAN_BLK - 1) / SCAN_BLK;

    int nb_gemm = (n + 63) / 64;
    int nb_scat = (nb_gemm + 2) / 3;
    int nb_fused = 4 * nb_scat;

    static void* deg_ptr = nullptr;
    static int smem_set = 0;
    if (!smem_set) {
        cudaFuncSetAttribute(k_gemm_scatter, cudaFuncAttributeMaxDynamicSharedMemorySize, 110 * 1024);
        cudaGetSymbolAddress(&deg_ptr, g_deg);
        smem_set = 1;
    }
    size_t gemm_smem = (size_t)(128 * WS_STRIDE + 64 * WS_STRIDE) * sizeof(uint32);

    cudaMemsetAsync(deg_ptr, 0, (size_t)n * sizeof(int));
    k_prep<<<(etot + 255) / 256, 256>>>(ei, e, n);
    k_scan1<<<nscan, SCAN_BLK>>>(n);
    k_scan23<<<nscan, SCAN_BLK>>>(n);
    k_gemm_scatter<<<nb_fused, 256, gemm_smem>>>(x, W, att_s, att_d, ei, n, e, nb_gemm, nb_scat);
    k_gather_final<<<GATHER_BLOCKS, 512>>>(bias, Wl, bl, out, n, GATHER_BLOCKS * 16);
}